// round 8
// baseline (speedup 1.0000x reference)
#include <cuda_runtime.h>

#define N_NODES   50000
#define N_EDGES   600000
#define FEA       128
#define NLAYER    3
#define NG        256
#define HDIM      256
#define LDIM      2
#define TOT_ADJ   (N_EDGES + N_NODES)

// ---------------- scratch (device globals; no allocation allowed) -------------
__device__ __align__(16) float g_h[N_NODES * FEA];   // post-GEMM features
__device__ __align__(16) float g_x[N_NODES * FEA];   // post-aggregation features
__device__ float g_dinv[N_NODES];
__device__ int   g_deg[N_NODES];
__device__ int   g_rowptr[N_NODES + 1];
__device__ int   g_cursor[N_NODES];
__device__ int   g_col[TOT_ADJ];
__device__ float g_val[TOT_ADJ];
__device__ int   g_start[NG + 1];
__device__ __align__(16) float g_pooled[NG * FEA];
__device__ __align__(16) float g_hidden[NG * HDIM];
__device__ int   g_is64;

// index helper: element i of a buffer that is either int32 or int64(LE, small)
__device__ __forceinline__ int ld_idx(const int* p, int i, int is64) {
    return is64 ? p[2 * i] : p[i];       // low word (values < 2^31)
}

// ---------------- dtype detection --------------------------------------------
// int64 little-endian with small values => every odd 32-bit word is 0
__global__ void k_detect(const int* __restrict__ ei) {
    int acc = 0;
    #pragma unroll
    for (int i = 1; i < 256; i += 2) acc |= ei[i];
    g_is64 = (acc == 0) ? 1 : 0;
}

// ---------------- CSR build ---------------------------------------------------
__global__ void k_init() {
    int i = blockIdx.x * blockDim.x + threadIdx.x;
    if (i < N_NODES) { g_deg[i] = 1; g_cursor[i] = 0; }   // 1 = self loop
}

__global__ void k_count(const int* __restrict__ ei) {
    int e = blockIdx.x * blockDim.x + threadIdx.x;
    if (e < N_EDGES) atomicAdd(&g_deg[ld_idx(ei, N_EDGES + e, g_is64)], 1);
}

__global__ void k_dinv() {
    int i = blockIdx.x * blockDim.x + threadIdx.x;
    if (i < N_NODES) g_dinv[i] = rsqrtf((float)g_deg[i]);
}

// single-block exclusive scan of g_deg -> g_rowptr
__global__ void k_scan() {
    __shared__ int s[1024];
    const int t = threadIdx.x;
    const int CH = (N_NODES + 1023) / 1024;          // 49
    int b = t * CH;
    int e = min(b + CH, N_NODES);
    int sum = 0;
    for (int i = b; i < e; i++) sum += g_deg[i];
    s[t] = sum;
    __syncthreads();
    for (int off = 1; off < 1024; off <<= 1) {
        int v = (t >= off) ? s[t - off] : 0;
        __syncthreads();
        s[t] += v;
        __syncthreads();
    }
    int excl = s[t] - sum;
    for (int i = b; i < e; i++) { g_rowptr[i] = excl; excl += g_deg[i]; }
    if (t == 1023) g_rowptr[N_NODES] = s[1023];
}

__global__ void k_fill(const int* __restrict__ ei) {
    int t = blockIdx.x * blockDim.x + threadIdx.x;
    int s, d;
    if (t < N_EDGES) {
        int is64 = g_is64;
        s = ld_idx(ei, t, is64);
        d = ld_idx(ei, N_EDGES + t, is64);
    } else if (t < TOT_ADJ) {
        s = d = t - N_EDGES;                  // self loop
    } else return;
    int idx = g_rowptr[d] + atomicAdd(&g_cursor[d], 1);
    g_col[idx] = s;
    g_val[idx] = g_dinv[s] * g_dinv[d];
}

// ---------------- GEMM: g_h[M,128] = A[M,128] @ W[128,128] --------------------
// block: 256 threads, tile 64 rows x 128 cols, W fully in smem.
#define GEMM_SMEM ((128 * 128 + 16 * 68) * 4)
__global__ void k_gemm(const float* __restrict__ A, const float* __restrict__ W) {
    extern __shared__ float smem[];
    float* Ws = smem;                 // [128][128]
    float* As = smem + 128 * 128;     // [16][68] padded

    if (A == nullptr) A = g_x;        // layers 1,2 read the device-global buffer

    const int tid = threadIdx.x;
    // load full W tile (64 KB) — float4, 16 per thread
    {
        const float4* W4 = (const float4*)W;
        float4* Ws4 = (float4*)Ws;
        #pragma unroll
        for (int i = 0; i < 16; i++) Ws4[tid + i * 256] = W4[tid + i * 256];
    }

    const int tx = tid & 15;          // col group (8 cols)
    const int ty = tid >> 4;          // row group (4 rows)
    const int base = blockIdx.x * 64;

    float acc[4][8];
    #pragma unroll
    for (int i = 0; i < 4; i++)
        #pragma unroll
        for (int j = 0; j < 8; j++) acc[i][j] = 0.f;

    const int lr = tid >> 2;          // 0..63 row within tile for loading
    const int lq = tid & 3;           // 0..3  k-quad for loading
    const int gr = min(base + lr, N_NODES - 1);

    for (int k0 = 0; k0 < 128; k0 += 16) {
        __syncthreads();
        float4 v = *(const float4*)&A[gr * 128 + k0 + lq * 4];
        As[(lq * 4 + 0) * 68 + lr] = v.x;
        As[(lq * 4 + 1) * 68 + lr] = v.y;
        As[(lq * 4 + 2) * 68 + lr] = v.z;
        As[(lq * 4 + 3) * 68 + lr] = v.w;
        __syncthreads();

        #pragma unroll
        for (int kk = 0; kk < 16; kk++) {
            float4 a4 = *(const float4*)&As[kk * 68 + ty * 4];
            float4 b0 = *(const float4*)&Ws[(k0 + kk) * 128 + tx * 8];      // FIX: k0+kk
            float4 b1 = *(const float4*)&Ws[(k0 + kk) * 128 + tx * 8 + 4];  // FIX: k0+kk
            float a[4] = {a4.x, a4.y, a4.z, a4.w};
            float bb[8] = {b0.x, b0.y, b0.z, b0.w, b1.x, b1.y, b1.z, b1.w};
            #pragma unroll
            for (int i = 0; i < 4; i++)
                #pragma unroll
                for (int j = 0; j < 8; j++)
                    acc[i][j] = fmaf(a[i], bb[j], acc[i][j]);
        }
    }

    #pragma unroll
    for (int i = 0; i < 4; i++) {
        int row = base + ty * 4 + i;
        if (row < N_NODES) {
            float4 o0 = make_float4(acc[i][0], acc[i][1], acc[i][2], acc[i][3]);
            float4 o1 = make_float4(acc[i][4], acc[i][5], acc[i][6], acc[i][7]);
            *(float4*)&g_h[row * 128 + tx * 8]     = o0;
            *(float4*)&g_h[row * 128 + tx * 8 + 4] = o1;
        }
    }
}

// ---------------- CSR aggregation: g_x[v] = relu(sum_j val*h[col] + bg) -------
// one warp per dst node, each lane owns 4 features (float4)
__global__ void k_agg(const float* __restrict__ bgl) {
    int warp = (blockIdx.x * blockDim.x + threadIdx.x) >> 5;
    int lane = threadIdx.x & 31;
    if (warp >= N_NODES) return;
    int r0 = g_rowptr[warp], r1 = g_rowptr[warp + 1];
    float ax = 0.f, ay = 0.f, az = 0.f, aw = 0.f;
    for (int j = r0; j < r1; j++) {
        int   s = g_col[j];
        float w = g_val[j];
        float4 hv = *(const float4*)&g_h[s * 128 + lane * 4];
        ax = fmaf(w, hv.x, ax);
        ay = fmaf(w, hv.y, ay);
        az = fmaf(w, hv.z, az);
        aw = fmaf(w, hv.w, aw);
    }
    float4 b = *(const float4*)&bgl[lane * 4];
    float4 o;
    o.x = fmaxf(ax + b.x, 0.f);
    o.y = fmaxf(ay + b.y, 0.f);
    o.z = fmaxf(az + b.z, 0.f);
    o.w = fmaxf(aw + b.w, 0.f);
    *(float4*)&g_x[warp * 128 + lane * 4] = o;
}

// ---------------- pooling -----------------------------------------------------
__global__ void k_start(const int* __restrict__ batch) {
    int g = blockIdx.x * blockDim.x + threadIdx.x;
    if (g > NG) return;
    int is64 = g_is64;
    int lo = 0, hi = N_NODES;
    while (lo < hi) {
        int mid = (lo + hi) >> 1;
        if (ld_idx(batch, mid, is64) < g) lo = mid + 1; else hi = mid;
    }
    g_start[g] = lo;
}

__global__ void k_pool() {
    int g = blockIdx.x, f = threadIdx.x;   // 128 threads
    int s = g_start[g], e = g_start[g + 1];
    float sum = 0.f;
    for (int n = s; n < e; n++) sum += g_x[n * 128 + f];
    int c = e - s;
    g_pooled[g * 128 + f] = sum / (float)max(c, 1);
}

// ---------------- MLP head ----------------------------------------------------
__global__ void k_mlp1(const float* __restrict__ w1, const float* __restrict__ b1) {
    __shared__ float pr[128];
    int g = blockIdx.x, j = threadIdx.x;   // 256 threads
    if (j < 128) pr[j] = g_pooled[g * 128 + j];
    __syncthreads();
    float acc = b1[j];
    #pragma unroll 4
    for (int k = 0; k < 128; k++) acc = fmaf(pr[k], w1[k * 256 + j], acc);
    g_hidden[g * 256 + j] = fmaxf(acc, 0.f);
}

__global__ void k_mlp2(const float* __restrict__ w2, const float* __restrict__ b2,
                       float* __restrict__ out) {
    int g = blockIdx.x;
    int w = threadIdx.x >> 5;     // output index 0..1 (block = 64 threads)
    int lane = threadIdx.x & 31;
    float acc = 0.f;
    #pragma unroll
    for (int k = lane; k < 256; k += 32)
        acc = fmaf(g_hidden[g * 256 + k], w2[k * 2 + w], acc);
    #pragma unroll
    for (int off = 16; off; off >>= 1)
        acc += __shfl_down_sync(0xffffffffu, acc, off);
    if (lane == 0) out[g * 2 + w] = acc + b2[w];
}

// ---------------- launch ------------------------------------------------------
extern "C" void kernel_launch(void* const* d_in, const int* in_sizes, int n_in,
                              void* d_out, int out_size) {
    // Identify inputs by element count (all distinct) — robust to ordering.
    const float *x = 0, *Wg = 0, *bg = 0, *w1 = 0, *b1 = 0, *w2 = 0, *b2 = 0;
    const int *ei = 0, *batch = 0;
    for (int i = 0; i < n_in; i++) {
        switch (in_sizes[i]) {
            case N_NODES * FEA:        x     = (const float*)d_in[i]; break; // 6.4M
            case NLAYER * FEA * FEA:   Wg    = (const float*)d_in[i]; break; // 49152
            case NLAYER * FEA:         bg    = (const float*)d_in[i]; break; // 384
            case FEA * HDIM:           w1    = (const float*)d_in[i]; break; // 32768
            case HDIM:                 b1    = (const float*)d_in[i]; break; // 256
            case HDIM * LDIM:          w2    = (const float*)d_in[i]; break; // 512
            case LDIM:                 b2    = (const float*)d_in[i]; break; // 2
            case 2 * N_EDGES:          ei    = (const int*)d_in[i];   break; // 1.2M
            case N_NODES:              batch = (const int*)d_in[i];   break; // 50000
        }
    }
    float* out = (float*)d_out;

    cudaFuncSetAttribute(k_gemm, cudaFuncAttributeMaxDynamicSharedMemorySize,
                         GEMM_SMEM);

    k_detect<<<1, 1>>>(ei);
    k_init <<<(N_NODES + 255) / 256, 256>>>();
    k_count<<<(N_EDGES + 255) / 256, 256>>>(ei);
    k_dinv <<<(N_NODES + 255) / 256, 256>>>();
    k_scan <<<1, 1024>>>();
    k_fill <<<(TOT_ADJ + 255) / 256, 256>>>(ei);

    for (int l = 0; l < NLAYER; l++) {
        const float* A = (l == 0) ? x : nullptr;   // nullptr -> g_x inside kernel
        k_gemm<<<(N_NODES + 63) / 64, 256, GEMM_SMEM>>>(A, Wg + l * FEA * FEA);
        k_agg <<<(N_NODES * 32 + 255) / 256, 256>>>(bg + l * FEA);
    }

    k_start<<<2, 256>>>(batch);
    k_pool <<<NG, 128>>>();
    k_mlp1 <<<NG, 256>>>(w1, b1);
    k_mlp2 <<<NG, 64>>>(w2, b2, out);
}